// round 7
// baseline (speedup 1.0000x reference)
#include <cuda_runtime.h>
#include <math.h>

#define NMAX   50000
#define EMAX   800000
#define KDIM   128
#define COUT   40
#define BN_EPS 1e-5f

#define SCAN_B 64
#define SCAN_T 256

#define GT_ROWS 128   // gemm block tile rows
#define GT_KC   32    // gemm k-chunk

#define AGG_BLOCKS 592

// ---------------- scratch (static device globals; no allocation) ----------------
// g_deg starts zeroed (static init); k_scatter re-zeros it every run AFTER the
// scans consume it. g_stats1/2 re-zeroed by the last kernel each run.
__device__ float g_buf1[NMAX * KDIM];
__device__ float g_buf2[NMAX * KDIM];
__device__ float g_dinv[NMAX];
__device__ int   g_deg [NMAX];
__device__ int   g_rowptr[NMAX + 1];
__device__ int   g_cursor[NMAX];
__device__ int2  g_edge[EMAX];          // {src, nrm bits}
__device__ float g_Wq1 [KDIM * KDIM];
__device__ float g_Wq2 [KDIM * KDIM];
__device__ float g_Wq3 [KDIM * COUT];
__device__ float g_stats1[2 * KDIM];
__device__ float g_stats2[2 * KDIM];
__device__ int   g_tpref[SCAN_B * SCAN_T];
__device__ int   g_bsum [SCAN_B];

// ---------------- f32x2 packed math ----------------
__device__ __forceinline__ unsigned long long pack2(float x) {
    unsigned long long r;
    asm("mov.b64 %0, {%1, %1};" : "=l"(r) : "f"(x));
    return r;
}
__device__ __forceinline__ unsigned long long ffma2(unsigned long long a,
                                                    unsigned long long b,
                                                    unsigned long long c) {
    unsigned long long d;
    asm("fma.rn.f32x2 %0, %1, %2, %3;" : "=l"(d) : "l"(a), "l"(b), "l"(c));
    return d;
}

// ------- pre: weight fake-quants + degree count -------
__global__ void k_pre(const int* __restrict__ dst, int* __restrict__ deg, int E,
                      const float* __restrict__ W1, const float* __restrict__ a1,
                      const float* __restrict__ W2, const float* __restrict__ a2,
                      const float* __restrict__ W3, const float* __restrict__ a3,
                      float* __restrict__ Q1, float* __restrict__ Q2,
                      float* __restrict__ Q3) {
    int i = blockIdx.x * blockDim.x + threadIdx.x;
    const int n12 = KDIM * KDIM, n3 = KDIM * COUT;
    if (i < n12) {
        float s = a1[0];
        Q1[i] = rintf(fminf(fmaxf(W1[i] / s, -8.0f), 7.0f)) * s;
        float s2v = a2[0];
        Q2[i] = rintf(fminf(fmaxf(W2[i] / s2v, -8.0f), 7.0f)) * s2v;
    }
    if (i < n3) {
        float s = a3[0];
        Q3[i] = rintf(fminf(fmaxf(W3[i] / s, -8.0f), 7.0f)) * s;
    }
    if (i < E) atomicAdd(&deg[dst[i]], 1);
}

// ---------------- parallel CSR scan; p1 also computes dinv ----------------
__device__ __forceinline__ void chunk_range(int n, int b, int t, int& s, int& e) {
    int chunkB = (n + SCAN_B - 1) / SCAN_B;
    int bstart = b * chunkB;
    int bend = min(bstart + chunkB, n);
    int chunkT = (chunkB + SCAN_T - 1) / SCAN_T;
    s = min(bstart + t * chunkT, bend);
    e = min(s + chunkT, bend);
}

__global__ void k_scan_p1(const int* __restrict__ deg, float* __restrict__ dinv,
                          int* __restrict__ tpref, int* __restrict__ bsum, int n) {
    int b = blockIdx.x, t = threadIdx.x;
    int s, e; chunk_range(n, b, t, s, e);
    int acc = 0;
    for (int i = s; i < e; i++) {
        int d = deg[i] + 1;               // +1 self loop (deg holds edge count)
        dinv[i] = rsqrtf((float)d);
        acc += d - 1;
    }
    int lane = t & 31, wid = t >> 5;
    int v = acc;
#pragma unroll
    for (int o = 1; o < 32; o <<= 1) {
        int u = __shfl_up_sync(0xffffffffu, v, o);
        if (lane >= o) v += u;
    }
    __shared__ int ws[8];
    if (lane == 31) ws[wid] = v;
    __syncthreads();
    if (t < 8) {
        int w = ws[t];
#pragma unroll
        for (int o = 1; o < 8; o <<= 1) {
            int u = __shfl_up_sync(0xffu, w, o);
            if (t >= o) w += u;
        }
        ws[t] = w;
    }
    __syncthreads();
    int excl = (v - acc) + (wid > 0 ? ws[wid - 1] : 0);
    tpref[b * SCAN_T + t] = excl;
    if (t == SCAN_T - 1) bsum[b] = excl + acc;
}

// p3 with embedded 64-wide scan of bsum
__global__ void k_scan_p3(const int* __restrict__ deg, const int* __restrict__ tpref,
                          const int* __restrict__ bsum, int* __restrict__ rowptr,
                          int* __restrict__ cursor, int n, int E) {
    int b = blockIdx.x, t = threadIdx.x;
    __shared__ int sb[SCAN_B];
    __shared__ int w0tot;
    if (t < SCAN_B) {
        int orig = bsum[t];
        int lane = t & 31;
        int v = orig;
#pragma unroll
        for (int o = 1; o < 32; o <<= 1) {
            int u = __shfl_up_sync(0xffffffffu, v, o);
            if (lane >= o) v += u;
        }
        if (t == 31) w0tot = v;
        __syncwarp();
        sb[t] = v - orig;
    }
    __syncthreads();
    if (t >= 32 && t < SCAN_B) sb[t] += w0tot;
    __syncthreads();

    int s, e; chunk_range(n, b, t, s, e);
    int run = sb[b] + tpref[b * SCAN_T + t];
    for (int i = s; i < e; i++) {
        rowptr[i] = run;
        cursor[i] = run;
        run += deg[i];      // deg = edge count (no self loop)
    }
    if (b == 0 && t == 0) rowptr[n] = E;
}

// scatter also re-zeros deg for the next run
__global__ void k_scatter(const int* __restrict__ src, const int* __restrict__ dst,
                          const float* __restrict__ dinv,
                          int* cursor, int2* __restrict__ edge, int* __restrict__ deg,
                          int E, int n) {
    int e = blockIdx.x * blockDim.x + threadIdx.x;
    if (e < n) deg[e] = 0;
    if (e >= E) return;
    int s = src[e], d = dst[e];
    int pos = atomicAdd(&cursor[d], 1);
    edge[pos] = make_int2(s, __float_as_int(dinv[s] * dinv[d]));
}

// ---- tiled GEMM NC=128: 128x128 block tile, 8x8 per thread, f32x2 FMA ----
template <bool FUSE>
__global__ __launch_bounds__(256, 2) void k_gemm_tiled(
        const float* __restrict__ X, const float* __restrict__ W,
        const float* __restrict__ B, float* __restrict__ out,
        const float* __restrict__ stats, const float* __restrict__ bng,
        const float* __restrict__ bnb, const float* __restrict__ gq, int N) {
    __shared__ float Ws[GT_KC][KDIM];          // 16KB
    __shared__ float Xs[GT_ROWS][GT_KC];       // 16KB
    __shared__ float scs[2 * KDIM];
    int tid  = threadIdx.x;
    int tx   = tid & 15;          // col group: 8 cols each
    int ty   = tid >> 4;          // row group: 8 rows each
    int rb   = ty * 8;
    int cb   = tx * 8;
    int row0 = blockIdx.x * GT_ROWS;

    if (FUSE) {
        if (tid < KDIM) {
            float inv_n = 1.0f / (float)N;
            float mean = stats[tid] * inv_n;
            float var  = stats[KDIM + tid] * inv_n - mean * mean;
            float scale = bng[tid] * rsqrtf(var + BN_EPS);
            scs[tid] = scale;
            scs[KDIM + tid] = bnb[tid] - mean * scale;
        }
        __syncthreads();
    }

    unsigned long long acc[8][4];   // [row][col-pair]
#pragma unroll
    for (int r = 0; r < 8; r++)
#pragma unroll
        for (int c = 0; c < 4; c++) acc[r][c] = 0ull;

    for (int kc = 0; kc < KDIM; kc += GT_KC) {
        // W chunk: GT_KC x 128 floats (4096) = 4 float4 per thread, coalesced
        for (int i = tid; i < GT_KC * (KDIM / 4); i += 256) {
            int k = i >> 5, c4 = i & 31;
            ((float4*)&Ws[k][0])[c4] =
                ((const float4*)(W + (size_t)(kc + k) * KDIM))[c4];
        }
        // X tile: GT_ROWS x GT_KC floats, row-major
        for (int i = tid; i < GT_ROWS * (GT_KC / 4); i += 256) {
            int r = i >> 3;           // GT_KC/4 = 8
            int kq = i & 7;
            int grow = row0 + r;
            float4 v = make_float4(0.f, 0.f, 0.f, 0.f);
            if (grow < N) {
                v = *((const float4*)(X + (size_t)grow * KDIM + kc) + kq);
                if (FUSE) {
                    float g = gq[grow];
                    float vv[4] = {v.x, v.y, v.z, v.w};
#pragma unroll
                    for (int u = 0; u < 4; u++) {
                        int c = kc + kq * 4 + u;
                        float t = fmaxf(fmaf(vv[u], scs[c], scs[KDIM + c]), 0.f);
                        vv[u] = rintf(fminf(t / g, 15.f)) * g;
                    }
                    v = make_float4(vv[0], vv[1], vv[2], vv[3]);
                }
            }
            ((float4*)&Xs[r][0])[kq] = v;
        }
        __syncthreads();
#pragma unroll 4
        for (int k = 0; k < GT_KC; k++) {
            ulonglong2 wp0 = *(const ulonglong2*)&Ws[k][cb];
            ulonglong2 wp1 = *(const ulonglong2*)&Ws[k][cb + 4];
#pragma unroll
            for (int r = 0; r < 8; r++) {
                unsigned long long xp = pack2(Xs[rb + r][k]);
                acc[r][0] = ffma2(xp, wp0.x, acc[r][0]);
                acc[r][1] = ffma2(xp, wp0.y, acc[r][1]);
                acc[r][2] = ffma2(xp, wp1.x, acc[r][2]);
                acc[r][3] = ffma2(xp, wp1.y, acc[r][3]);
            }
        }
        __syncthreads();
    }
    float4 bb0 = *(const float4*)(B + cb);
    float4 bb1 = *(const float4*)(B + cb + 4);
#pragma unroll
    for (int r = 0; r < 8; r++) {
        int grow = row0 + rb + r;
        if (grow < N) {
            float4 o0, o1;
            o0.x = __uint_as_float((unsigned)(acc[r][0]))       + bb0.x;
            o0.y = __uint_as_float((unsigned)(acc[r][0] >> 32)) + bb0.y;
            o0.z = __uint_as_float((unsigned)(acc[r][1]))       + bb0.z;
            o0.w = __uint_as_float((unsigned)(acc[r][1] >> 32)) + bb0.w;
            o1.x = __uint_as_float((unsigned)(acc[r][2]))       + bb1.x;
            o1.y = __uint_as_float((unsigned)(acc[r][2] >> 32)) + bb1.y;
            o1.z = __uint_as_float((unsigned)(acc[r][3]))       + bb1.z;
            o1.w = __uint_as_float((unsigned)(acc[r][3] >> 32)) + bb1.w;
            *((float4*)(out + (size_t)grow * KDIM + cb))     = o0;
            *((float4*)(out + (size_t)grow * KDIM + cb + 4)) = o1;
        }
    }
}

// ---------------- warp-per-row GEMM (NC=40), fused BN+ReLU+fq prologue ----------
__global__ __launch_bounds__(256) void k_gemm40(
        const float* __restrict__ X, const float* __restrict__ W,
        const float* __restrict__ B, float* __restrict__ out,
        const float* __restrict__ stats, const float* __restrict__ bng,
        const float* __restrict__ bnb, const float* __restrict__ gq, int N) {
    __shared__ float scs[2 * KDIM];
    int tid = threadIdx.x;
    if (tid < KDIM) {
        float inv_n = 1.0f / (float)N;
        float mean = stats[tid] * inv_n;
        float var  = stats[KDIM + tid] * inv_n - mean * mean;
        float scale = bng[tid] * rsqrtf(var + BN_EPS);
        scs[tid] = scale;
        scs[KDIM + tid] = bnb[tid] - mean * scale;
    }
    __syncthreads();

    int warp = (blockIdx.x * blockDim.x + tid) >> 5;
    int lane = tid & 31;
    if (warp >= N) return;
    const float* xr = X + (size_t)warp * KDIM;
    float xv[4];
    float g = gq[warp];
#pragma unroll
    for (int i = 0; i < 4; i++) {
        int c = lane + 32 * i;
        float v = fmaxf(fmaf(xr[c], scs[c], scs[KDIM + c]), 0.f);
        xv[i] = rintf(fminf(v / g, 15.0f)) * g;
    }
    bool active = (lane * 4) < COUT;
    int col = active ? lane * 4 : 0;
    float ax = 0.f, ay = 0.f, az = 0.f, aw = 0.f;
#pragma unroll
    for (int k = 0; k < KDIM; k++) {
        float s = (k < 32) ? xv[0] : (k < 64) ? xv[1] : (k < 96) ? xv[2] : xv[3];
        float xk = __shfl_sync(0xffffffffu, s, k & 31);
        float4 w = *(const float4*)(W + (size_t)k * COUT + col);
        ax = fmaf(xk, w.x, ax); ay = fmaf(xk, w.y, ay);
        az = fmaf(xk, w.z, az); aw = fmaf(xk, w.w, aw);
    }
    if (active) {
        float4 bb = *(const float4*)(B + col);
        float* o = out + (size_t)warp * COUT + col;
        o[0] = ax + bb.x; o[1] = ay + bb.y; o[2] = az + bb.z; o[3] = aw + bb.w;
    }
}

// ---- CSR aggregation C=128, grid-stride warp/node, direct ldg unroll-4 (R5) ----
__global__ __launch_bounds__(256) void k_agg_csr128_stats(
        const int* __restrict__ rowptr, const int2* __restrict__ edge,
        const float* __restrict__ dinv,
        const float* __restrict__ in, float* __restrict__ out,
        float* __restrict__ stats, int n) {
    int tid = threadIdx.x;
    int lane = tid & 31;
    int warp0 = (blockIdx.x * blockDim.x + tid) >> 5;
    int nwarps = (gridDim.x * blockDim.x) >> 5;
    int c0 = lane * 4;

    __shared__ float ssum[KDIM], ssq[KDIM];
    if (tid < KDIM) { ssum[tid] = 0.f; ssq[tid] = 0.f; }
    __syncthreads();

    float lsum[4] = {0.f, 0.f, 0.f, 0.f};
    float lsq [4] = {0.f, 0.f, 0.f, 0.f};

    for (int node = warp0; node < n; node += nwarps) {
        int beg = rowptr[node], end = rowptr[node + 1];
        float dd = dinv[node]; dd *= dd;
        float4 v = __ldg((const float4*)(in + (size_t)node * KDIM) + lane);
        float4 acc = make_float4(dd * v.x, dd * v.y, dd * v.z, dd * v.w);
        int j = beg;
        for (; j + 4 <= end; j += 4) {
            int2 e0 = __ldg(edge + j),     e1 = __ldg(edge + j + 1);
            int2 e2 = __ldg(edge + j + 2), e3 = __ldg(edge + j + 3);
            float w0 = __int_as_float(e0.y), w1 = __int_as_float(e1.y);
            float w2 = __int_as_float(e2.y), w3 = __int_as_float(e3.y);
            float4 m0 = __ldg((const float4*)(in + (size_t)e0.x * KDIM) + lane);
            float4 m1 = __ldg((const float4*)(in + (size_t)e1.x * KDIM) + lane);
            float4 m2 = __ldg((const float4*)(in + (size_t)e2.x * KDIM) + lane);
            float4 m3 = __ldg((const float4*)(in + (size_t)e3.x * KDIM) + lane);
            acc.x = fmaf(w0, m0.x, fmaf(w1, m1.x, fmaf(w2, m2.x, fmaf(w3, m3.x, acc.x))));
            acc.y = fmaf(w0, m0.y, fmaf(w1, m1.y, fmaf(w2, m2.y, fmaf(w3, m3.y, acc.y))));
            acc.z = fmaf(w0, m0.z, fmaf(w1, m1.z, fmaf(w2, m2.z, fmaf(w3, m3.z, acc.z))));
            acc.w = fmaf(w0, m0.w, fmaf(w1, m1.w, fmaf(w2, m2.w, fmaf(w3, m3.w, acc.w))));
        }
        for (; j < end; j++) {
            int2 e0 = __ldg(edge + j);
            float w0 = __int_as_float(e0.y);
            float4 m0 = __ldg((const float4*)(in + (size_t)e0.x * KDIM) + lane);
            acc.x = fmaf(w0, m0.x, acc.x); acc.y = fmaf(w0, m0.y, acc.y);
            acc.z = fmaf(w0, m0.z, acc.z); acc.w = fmaf(w0, m0.w, acc.w);
        }
        *((float4*)(out + (size_t)node * KDIM) + lane) = acc;
        lsum[0] += acc.x; lsum[1] += acc.y; lsum[2] += acc.z; lsum[3] += acc.w;
        lsq[0] = fmaf(acc.x, acc.x, lsq[0]); lsq[1] = fmaf(acc.y, acc.y, lsq[1]);
        lsq[2] = fmaf(acc.z, acc.z, lsq[2]); lsq[3] = fmaf(acc.w, acc.w, lsq[3]);
    }
#pragma unroll
    for (int u = 0; u < 4; u++) {
        atomicAdd(&ssum[c0 + u], lsum[u]);
        atomicAdd(&ssq [c0 + u], lsq[u]);
    }
    __syncthreads();
    if (tid < KDIM) {
        atomicAdd(&stats[tid], ssum[tid]);
        atomicAdd(&stats[KDIM + tid], ssq[tid]);
    }
}

// ---- CSR aggregation C=40 + log-softmax; also re-zeros stats for next run ----
__global__ void k_agg40_lsm(const int* __restrict__ rowptr, const int2* __restrict__ edge,
                            const float* __restrict__ dinv,
                            const float* __restrict__ in, float* __restrict__ out,
                            float* __restrict__ st1, float* __restrict__ st2, int n) {
    int gtid = blockIdx.x * blockDim.x + threadIdx.x;
    if (gtid < 2 * KDIM) { st1[gtid] = 0.f; st2[gtid] = 0.f; }
    int node = gtid >> 5;
    int lane = threadIdx.x & 31;
    if (node >= n) return;
    int beg = rowptr[node], end = rowptr[node + 1];
    float dd = dinv[node]; dd *= dd;
    const float* r0 = in + (size_t)node * COUT;
    float accA = dd * __ldg(r0 + lane);
    float accB = (lane < 8) ? dd * __ldg(r0 + 32 + lane) : 0.f;
    int j = beg;
    for (; j + 2 <= end; j += 2) {
        int2 e0 = __ldg(edge + j), e1 = __ldg(edge + j + 1);
        float w0 = __int_as_float(e0.y), w1 = __int_as_float(e1.y);
        const float* rs0 = in + (size_t)e0.x * COUT;
        const float* rs1 = in + (size_t)e1.x * COUT;
        accA = fmaf(w0, __ldg(rs0 + lane), fmaf(w1, __ldg(rs1 + lane), accA));
        if (lane < 8)
            accB = fmaf(w0, __ldg(rs0 + 32 + lane), fmaf(w1, __ldg(rs1 + 32 + lane), accB));
    }
    if (j < end) {
        int2 e0 = __ldg(edge + j);
        float w = __int_as_float(e0.y);
        const float* rs = in + (size_t)e0.x * COUT;
        accA = fmaf(w, __ldg(rs + lane), accA);
        if (lane < 8) accB = fmaf(w, __ldg(rs + 32 + lane), accB);
    }
    float b = (lane < 8) ? accB : -INFINITY;
    float mx = fmaxf(accA, b);
#pragma unroll
    for (int o = 16; o > 0; o >>= 1) mx = fmaxf(mx, __shfl_xor_sync(0xffffffffu, mx, o));
    float s = expf(accA - mx) + ((lane < 8) ? expf(accB - mx) : 0.f);
#pragma unroll
    for (int o = 16; o > 0; o >>= 1) s += __shfl_xor_sync(0xffffffffu, s, o);
    float ls = logf(s);
    float* w = out + (size_t)node * COUT;
    w[lane] = accA - mx - ls;
    if (lane < 8) w[32 + lane] = accB - mx - ls;
}

// ---------------- host ----------------
static inline int cdiv(int a, int b) { return (a + b - 1) / b; }

extern "C" void kernel_launch(void* const* d_in, const int* in_sizes, int n_in,
                              void* d_out, int out_size) {
    const float* x    = (const float*)d_in[0];
    const int*   ei   = (const int*)d_in[1];
    const float* W1   = (const float*)d_in[2];
    const float* b1   = (const float*)d_in[3];
    const float* a1   = (const float*)d_in[4];
    const float* W2   = (const float*)d_in[5];
    const float* b2   = (const float*)d_in[6];
    const float* a2   = (const float*)d_in[7];
    const float* g2   = (const float*)d_in[8];
    const float* W3   = (const float*)d_in[9];
    const float* b3   = (const float*)d_in[10];
    const float* a3   = (const float*)d_in[11];
    const float* g3   = (const float*)d_in[12];
    const float* bn1g = (const float*)d_in[13];
    const float* bn1b = (const float*)d_in[14];
    const float* bn2g = (const float*)d_in[15];
    const float* bn2b = (const float*)d_in[16];

    const int N = in_sizes[0] / KDIM;
    const int E = in_sizes[1] / 2;
    const int* src = ei;
    const int* dst = ei + E;

    float *buf1, *buf2, *dinv, *Wq1, *Wq2, *Wq3, *stats1, *stats2;
    int *deg, *rowptr, *cursor, *tpref, *bsum;
    int2* edge;
    cudaGetSymbolAddress((void**)&buf1,   g_buf1);
    cudaGetSymbolAddress((void**)&buf2,   g_buf2);
    cudaGetSymbolAddress((void**)&dinv,   g_dinv);
    cudaGetSymbolAddress((void**)&deg,    g_deg);
    cudaGetSymbolAddress((void**)&rowptr, g_rowptr);
    cudaGetSymbolAddress((void**)&cursor, g_cursor);
    cudaGetSymbolAddress((void**)&edge,   g_edge);
    cudaGetSymbolAddress((void**)&Wq1,    g_Wq1);
    cudaGetSymbolAddress((void**)&Wq2,    g_Wq2);
    cudaGetSymbolAddress((void**)&Wq3,    g_Wq3);
    cudaGetSymbolAddress((void**)&stats1, g_stats1);
    cudaGetSymbolAddress((void**)&stats2, g_stats2);
    cudaGetSymbolAddress((void**)&tpref,  g_tpref);
    cudaGetSymbolAddress((void**)&bsum,   g_bsum);

    const int TB = 256;
    const int GB = cdiv(N, GT_ROWS);

    k_pre<<<cdiv(E, TB), TB>>>(dst, deg, E, W1, a1, W2, a2, W3, a3, Wq1, Wq2, Wq3);
    k_scan_p1<<<SCAN_B, SCAN_T>>>(deg, dinv, tpref, bsum, N);
    k_scan_p3<<<SCAN_B, SCAN_T>>>(deg, tpref, bsum, rowptr, cursor, N, E);
    // layer-1 GEMM at launch index 3 (ncu capture target)
    k_gemm_tiled<false><<<GB, 256>>>(x, Wq1, b1, buf1, nullptr, nullptr, nullptr, nullptr, N);
    k_scatter<<<cdiv(E, TB), TB>>>(src, dst, dinv, cursor, edge, deg, E, N);

    // ---- layer 1 aggregation ----
    k_agg_csr128_stats<<<AGG_BLOCKS, 256>>>(rowptr, edge, dinv, buf1, buf2, stats1, N);

    // ---- layer 2 ----
    k_gemm_tiled<true><<<GB, 256>>>(buf2, Wq2, b2, buf1, stats1, bn1g, bn1b, g2, N);
    k_agg_csr128_stats<<<AGG_BLOCKS, 256>>>(rowptr, edge, dinv, buf1, buf2, stats2, N);

    // ---- layer 3 ----
    k_gemm40<<<cdiv(N * 32, TB), TB>>>(buf2, Wq3, b3, buf1, stats2, bn2g, bn2b, g3, N);
    k_agg40_lsm<<<cdiv(N * 32, TB), TB>>>(rowptr, edge, dinv, buf1, (float*)d_out,
                                          stats1, stats2, N);
}

// round 8
// speedup vs baseline: 1.0710x; 1.0710x over previous
#include <cuda_runtime.h>
#include <cuda_fp16.h>
#include <math.h>

#define NMAX   50000
#define EMAX   800000
#define KDIM   128
#define COUT   40
#define BN_EPS 1e-5f

#define SCAN_B 64
#define SCAN_T 256

#define TROWS  64   // gemm tile rows
#define KC     64   // gemm k-chunk

#define AGG_BLOCKS 592

// ---------------- scratch (static device globals; no allocation) ----------------
// g_deg starts zeroed; k_scatter re-zeros it every run AFTER the scans consume it.
// g_stats1/2 re-zeroed by the last kernel each run.
__device__ float  g_buf1[NMAX * KDIM];
__device__ float  g_buf2[NMAX * KDIM];
__device__ __half g_hbuf[NMAX * KDIM];   // fp16 message buffer (GEMM out -> agg in)
__device__ float  g_dinv[NMAX];
__device__ int    g_deg [NMAX];
__device__ int    g_rowptr[NMAX + 1];
__device__ int    g_cursor[NMAX];
__device__ int2   g_edge[EMAX];          // {src, nrm bits}
__device__ float  g_Wq1 [KDIM * KDIM];
__device__ float  g_Wq2 [KDIM * KDIM];
__device__ float  g_Wq3 [KDIM * COUT];
__device__ float  g_stats1[2 * KDIM];
__device__ float  g_stats2[2 * KDIM];
__device__ int    g_tpref[SCAN_B * SCAN_T];
__device__ int    g_bsum [SCAN_B];

// ---------------- f32x2 packed math ----------------
__device__ __forceinline__ unsigned long long pack2(float x) {
    unsigned long long r;
    asm("mov.b64 %0, {%1, %1};" : "=l"(r) : "f"(x));
    return r;
}
__device__ __forceinline__ unsigned long long ffma2(unsigned long long a,
                                                    unsigned long long b,
                                                    unsigned long long c) {
    unsigned long long d;
    asm("fma.rn.f32x2 %0, %1, %2, %3;" : "=l"(d) : "l"(a), "l"(b), "l"(c));
    return d;
}
__device__ __forceinline__ unsigned h2u(__half2 h) {
    return *reinterpret_cast<unsigned*>(&h);
}
__device__ __forceinline__ float2 u2f2(unsigned u) {
    __half2 h = *reinterpret_cast<__half2*>(&u);
    return __half22float2(h);
}

// ------- pre: weight fake-quants + degree count -------
__global__ void k_pre(const int* __restrict__ dst, int* __restrict__ deg, int E,
                      const float* __restrict__ W1, const float* __restrict__ a1,
                      const float* __restrict__ W2, const float* __restrict__ a2,
                      const float* __restrict__ W3, const float* __restrict__ a3,
                      float* __restrict__ Q1, float* __restrict__ Q2,
                      float* __restrict__ Q3) {
    int i = blockIdx.x * blockDim.x + threadIdx.x;
    const int n12 = KDIM * KDIM, n3 = KDIM * COUT;
    if (i < n12) {
        float s = a1[0];
        Q1[i] = rintf(fminf(fmaxf(W1[i] / s, -8.0f), 7.0f)) * s;
        float s2v = a2[0];
        Q2[i] = rintf(fminf(fmaxf(W2[i] / s2v, -8.0f), 7.0f)) * s2v;
    }
    if (i < n3) {
        float s = a3[0];
        Q3[i] = rintf(fminf(fmaxf(W3[i] / s, -8.0f), 7.0f)) * s;
    }
    if (i < E) atomicAdd(&deg[dst[i]], 1);
}

// ---------------- parallel CSR scan; p1 also computes dinv ----------------
__device__ __forceinline__ void chunk_range(int n, int b, int t, int& s, int& e) {
    int chunkB = (n + SCAN_B - 1) / SCAN_B;
    int bstart = b * chunkB;
    int bend = min(bstart + chunkB, n);
    int chunkT = (chunkB + SCAN_T - 1) / SCAN_T;
    s = min(bstart + t * chunkT, bend);
    e = min(s + chunkT, bend);
}

__global__ void k_scan_p1(const int* __restrict__ deg, float* __restrict__ dinv,
                          int* __restrict__ tpref, int* __restrict__ bsum, int n) {
    int b = blockIdx.x, t = threadIdx.x;
    int s, e; chunk_range(n, b, t, s, e);
    int acc = 0;
    for (int i = s; i < e; i++) {
        int d = deg[i] + 1;               // +1 self loop (deg holds edge count)
        dinv[i] = rsqrtf((float)d);
        acc += d - 1;
    }
    int lane = t & 31, wid = t >> 5;
    int v = acc;
#pragma unroll
    for (int o = 1; o < 32; o <<= 1) {
        int u = __shfl_up_sync(0xffffffffu, v, o);
        if (lane >= o) v += u;
    }
    __shared__ int ws[8];
    if (lane == 31) ws[wid] = v;
    __syncthreads();
    if (t < 8) {
        int w = ws[t];
#pragma unroll
        for (int o = 1; o < 8; o <<= 1) {
            int u = __shfl_up_sync(0xffu, w, o);
            if (t >= o) w += u;
        }
        ws[t] = w;
    }
    __syncthreads();
    int excl = (v - acc) + (wid > 0 ? ws[wid - 1] : 0);
    tpref[b * SCAN_T + t] = excl;
    if (t == SCAN_T - 1) bsum[b] = excl + acc;
}

__global__ void k_scan_p3(const int* __restrict__ deg, const int* __restrict__ tpref,
                          const int* __restrict__ bsum, int* __restrict__ rowptr,
                          int* __restrict__ cursor, int n, int E) {
    int b = blockIdx.x, t = threadIdx.x;
    __shared__ int sb[SCAN_B];
    __shared__ int w0tot;
    if (t < SCAN_B) {
        int orig = bsum[t];
        int lane = t & 31;
        int v = orig;
#pragma unroll
        for (int o = 1; o < 32; o <<= 1) {
            int u = __shfl_up_sync(0xffffffffu, v, o);
            if (lane >= o) v += u;
        }
        if (t == 31) w0tot = v;
        __syncwarp();
        sb[t] = v - orig;
    }
    __syncthreads();
    if (t >= 32 && t < SCAN_B) sb[t] += w0tot;
    __syncthreads();

    int s, e; chunk_range(n, b, t, s, e);
    int run = sb[b] + tpref[b * SCAN_T + t];
    for (int i = s; i < e; i++) {
        rowptr[i] = run;
        cursor[i] = run;
        run += deg[i];
    }
    if (b == 0 && t == 0) rowptr[n] = E;
}

__global__ void k_scatter(const int* __restrict__ src, const int* __restrict__ dst,
                          const float* __restrict__ dinv,
                          int* cursor, int2* __restrict__ edge, int* __restrict__ deg,
                          int E, int n) {
    int e = blockIdx.x * blockDim.x + threadIdx.x;
    if (e < n) deg[e] = 0;
    if (e >= E) return;
    int s = src[e], d = dst[e];
    int pos = atomicAdd(&cursor[d], 1);
    edge[pos] = make_int2(s, __float_as_int(dinv[s] * dinv[d]));
}

// ---- tiled GEMM NC=128 (R6 shape): 64x128 tile, 8x4/thread, f32x2, fp16 out ----
template <bool FUSE>
__global__ __launch_bounds__(256) void k_gemm_tiled(
        const float* __restrict__ X, const float* __restrict__ W,
        const float* __restrict__ B, __half* __restrict__ hout,
        const float* __restrict__ stats, const float* __restrict__ bng,
        const float* __restrict__ bnb, const float* __restrict__ gq, int N) {
    __shared__ float Ws[KC][KDIM];    // 32KB
    __shared__ float Xs[TROWS][KC];   // 16KB
    __shared__ float scs[2 * KDIM];
    int tid  = threadIdx.x;
    int lane = tid & 31;
    int rb   = (tid >> 5) * 8;
    int col  = lane * 4;
    int row0 = blockIdx.x * TROWS;

    if (FUSE) {
        if (tid < KDIM) {
            float inv_n = 1.0f / (float)N;
            float mean = stats[tid] * inv_n;
            float var  = stats[KDIM + tid] * inv_n - mean * mean;
            float scale = bng[tid] * rsqrtf(var + BN_EPS);
            scs[tid] = scale;
            scs[KDIM + tid] = bnb[tid] - mean * scale;
        }
        __syncthreads();
    }

    unsigned long long acc01[8], acc23[8];
#pragma unroll
    for (int r = 0; r < 8; r++) { acc01[r] = 0ull; acc23[r] = 0ull; }

    for (int kc = 0; kc < KDIM; kc += KC) {
        for (int i = tid; i < KC * (KDIM / 4); i += 256) {
            int k = i >> 5, c4 = i & 31;
            ((float4*)&Ws[k][0])[c4] =
                ((const float4*)(W + (size_t)(kc + k) * KDIM))[c4];
        }
        for (int i = tid; i < TROWS * (KC / 4); i += 256) {
            int r = i / (KC / 4);
            int kq = i % (KC / 4);
            int grow = row0 + r;
            float4 v = make_float4(0.f, 0.f, 0.f, 0.f);
            if (grow < N) {
                v = *((const float4*)(X + (size_t)grow * KDIM + kc) + kq);
                if (FUSE) {
                    float g = gq[grow];
                    float vv[4] = {v.x, v.y, v.z, v.w};
#pragma unroll
                    for (int u = 0; u < 4; u++) {
                        int c = kc + kq * 4 + u;
                        float t = fmaxf(fmaf(vv[u], scs[c], scs[KDIM + c]), 0.f);
                        vv[u] = rintf(fminf(t / g, 15.f)) * g;
                    }
                    v = make_float4(vv[0], vv[1], vv[2], vv[3]);
                }
            }
            ((float4*)&Xs[r][0])[kq] = v;
        }
        __syncthreads();
#pragma unroll 4
        for (int k = 0; k < KC; k += 2) {
            ulonglong2 w0 = *(const ulonglong2*)&Ws[k][col];
            ulonglong2 w1 = *(const ulonglong2*)&Ws[k + 1][col];
#pragma unroll
            for (int r = 0; r < 8; r++) {
                float2 xp = *(const float2*)&Xs[rb + r][k];   // LDS.64 broadcast
                unsigned long long xa = pack2(xp.x);
                unsigned long long xb = pack2(xp.y);
                acc01[r] = ffma2(xa, w0.x, acc01[r]);
                acc23[r] = ffma2(xa, w0.y, acc23[r]);
                acc01[r] = ffma2(xb, w1.x, acc01[r]);
                acc23[r] = ffma2(xb, w1.y, acc23[r]);
            }
        }
        __syncthreads();
    }
    float4 bb = *(const float4*)(B + col);
#pragma unroll
    for (int r = 0; r < 8; r++) {
        int grow = row0 + rb + r;
        if (grow < N) {
            float ox = __uint_as_float((unsigned)(acc01[r]))       + bb.x;
            float oy = __uint_as_float((unsigned)(acc01[r] >> 32)) + bb.y;
            float oz = __uint_as_float((unsigned)(acc23[r]))       + bb.z;
            float ow = __uint_as_float((unsigned)(acc23[r] >> 32)) + bb.w;
            uint2 st;
            st.x = h2u(__floats2half2_rn(ox, oy));
            st.y = h2u(__floats2half2_rn(oz, ow));
            *((uint2*)(hout + (size_t)grow * KDIM + col)) = st;
        }
    }
}

// ------- warp-per-row GEMM (NC=40), fused BN+ReLU+fq prologue, fp16 out -------
__global__ __launch_bounds__(256) void k_gemm40(
        const float* __restrict__ X, const float* __restrict__ W,
        const float* __restrict__ B, __half* __restrict__ hout,
        const float* __restrict__ stats, const float* __restrict__ bng,
        const float* __restrict__ bnb, const float* __restrict__ gq, int N) {
    __shared__ float scs[2 * KDIM];
    int tid = threadIdx.x;
    if (tid < KDIM) {
        float inv_n = 1.0f / (float)N;
        float mean = stats[tid] * inv_n;
        float var  = stats[KDIM + tid] * inv_n - mean * mean;
        float scale = bng[tid] * rsqrtf(var + BN_EPS);
        scs[tid] = scale;
        scs[KDIM + tid] = bnb[tid] - mean * scale;
    }
    __syncthreads();

    int warp = (blockIdx.x * blockDim.x + tid) >> 5;
    int lane = tid & 31;
    if (warp >= N) return;
    const float* xr = X + (size_t)warp * KDIM;
    float xv[4];
    float g = gq[warp];
#pragma unroll
    for (int i = 0; i < 4; i++) {
        int c = lane + 32 * i;
        float v = fmaxf(fmaf(xr[c], scs[c], scs[KDIM + c]), 0.f);
        xv[i] = rintf(fminf(v / g, 15.0f)) * g;
    }
    bool active = (lane * 4) < COUT;
    int col = active ? lane * 4 : 0;
    float ax = 0.f, ay = 0.f, az = 0.f, aw = 0.f;
#pragma unroll
    for (int k = 0; k < KDIM; k++) {
        float s = (k < 32) ? xv[0] : (k < 64) ? xv[1] : (k < 96) ? xv[2] : xv[3];
        float xk = __shfl_sync(0xffffffffu, s, k & 31);
        float4 w = *(const float4*)(W + (size_t)k * COUT + col);
        ax = fmaf(xk, w.x, ax); ay = fmaf(xk, w.y, ay);
        az = fmaf(xk, w.z, az); aw = fmaf(xk, w.w, aw);
    }
    if (active) {
        float4 bb = *(const float4*)(B + col);
        uint2 st;
        st.x = h2u(__floats2half2_rn(ax + bb.x, ay + bb.y));
        st.y = h2u(__floats2half2_rn(az + bb.z, aw + bb.w));
        *((uint2*)(hout + (size_t)warp * COUT + col)) = st;
    }
}

// ---- CSR aggregation C=128 (fp16 in, fp32 out), warp/node, fused BN stats ----
__global__ __launch_bounds__(256) void k_agg_csr128_stats(
        const int* __restrict__ rowptr, const int2* __restrict__ edge,
        const float* __restrict__ dinv,
        const __half* __restrict__ in, float* __restrict__ out,
        float* __restrict__ stats, int n) {
    int tid = threadIdx.x;
    int lane = tid & 31;
    int warp0 = (blockIdx.x * blockDim.x + tid) >> 5;
    int nwarps = (gridDim.x * blockDim.x) >> 5;
    int c0 = lane * 4;

    __shared__ float ssum[KDIM], ssq[KDIM];
    if (tid < KDIM) { ssum[tid] = 0.f; ssq[tid] = 0.f; }
    __syncthreads();

    float lsum[4] = {0.f, 0.f, 0.f, 0.f};
    float lsq [4] = {0.f, 0.f, 0.f, 0.f};

    for (int node = warp0; node < n; node += nwarps) {
        int beg = rowptr[node], end = rowptr[node + 1];
        float dd = dinv[node]; dd *= dd;
        uint2 uv = __ldg((const uint2*)(in + (size_t)node * KDIM) + lane);
        float2 va = u2f2(uv.x), vb = u2f2(uv.y);
        float4 acc = make_float4(dd * va.x, dd * va.y, dd * vb.x, dd * vb.y);
        int j = beg;
        for (; j + 4 <= end; j += 4) {
            int2 e0 = __ldg(edge + j),     e1 = __ldg(edge + j + 1);
            int2 e2 = __ldg(edge + j + 2), e3 = __ldg(edge + j + 3);
            float w0 = __int_as_float(e0.y), w1 = __int_as_float(e1.y);
            float w2 = __int_as_float(e2.y), w3 = __int_as_float(e3.y);
            uint2 u0 = __ldg((const uint2*)(in + (size_t)e0.x * KDIM) + lane);
            uint2 u1 = __ldg((const uint2*)(in + (size_t)e1.x * KDIM) + lane);
            uint2 u2v = __ldg((const uint2*)(in + (size_t)e2.x * KDIM) + lane);
            uint2 u3 = __ldg((const uint2*)(in + (size_t)e3.x * KDIM) + lane);
            float2 a0 = u2f2(u0.x), b0 = u2f2(u0.y);
            float2 a1 = u2f2(u1.x), b1 = u2f2(u1.y);
            float2 a2 = u2f2(u2v.x), b2 = u2f2(u2v.y);
            float2 a3 = u2f2(u3.x), b3 = u2f2(u3.y);
            acc.x = fmaf(w0, a0.x, fmaf(w1, a1.x, fmaf(w2, a2.x, fmaf(w3, a3.x, acc.x))));
            acc.y = fmaf(w0, a0.y, fmaf(w1, a1.y, fmaf(w2, a2.y, fmaf(w3, a3.y, acc.y))));
            acc.z = fmaf(w0, b0.x, fmaf(w1, b1.x, fmaf(w2, b2.x, fmaf(w3, b3.x, acc.z))));
            acc.w = fmaf(w0, b0.y, fmaf(w1, b1.y, fmaf(w2, b2.y, fmaf(w3, b3.y, acc.w))));
        }
        for (; j < end; j++) {
            int2 e0 = __ldg(edge + j);
            float w0 = __int_as_float(e0.y);
            uint2 u0 = __ldg((const uint2*)(in + (size_t)e0.x * KDIM) + lane);
            float2 a0 = u2f2(u0.x), b0 = u2f2(u0.y);
            acc.x = fmaf(w0, a0.x, acc.x); acc.y = fmaf(w0, a0.y, acc.y);
            acc.z = fmaf(w0, b0.x, acc.z); acc.w = fmaf(w0, b0.y, acc.w);
        }
        *((float4*)(out + (size_t)node * KDIM) + lane) = acc;
        lsum[0] += acc.x; lsum[1] += acc.y; lsum[2] += acc.z; lsum[3] += acc.w;
        lsq[0] = fmaf(acc.x, acc.x, lsq[0]); lsq[1] = fmaf(acc.y, acc.y, lsq[1]);
        lsq[2] = fmaf(acc.z, acc.z, lsq[2]); lsq[3] = fmaf(acc.w, acc.w, lsq[3]);
    }
#pragma unroll
    for (int u = 0; u < 4; u++) {
        atomicAdd(&ssum[c0 + u], lsum[u]);
        atomicAdd(&ssq [c0 + u], lsq[u]);
    }
    __syncthreads();
    if (tid < KDIM) {
        atomicAdd(&stats[tid], ssum[tid]);
        atomicAdd(&stats[KDIM + tid], ssq[tid]);
    }
}

// ---- CSR aggregation C=40 (fp16 in) + log-softmax; re-zeros stats ----
// lanes 0..19 each own 2 channels {2l, 2l+1}
__global__ void k_agg40_lsm(const int* __restrict__ rowptr, const int2* __restrict__ edge,
                            const float* __restrict__ dinv,
                            const __half* __restrict__ in, float* __restrict__ out,
                            float* __restrict__ st1, float* __restrict__ st2, int n) {
    int gtid = blockIdx.x * blockDim.x + threadIdx.x;
    if (gtid < 2 * KDIM) { st1[gtid] = 0.f; st2[gtid] = 0.f; }
    int node = gtid >> 5;
    int lane = threadIdx.x & 31;
    if (node >= n) return;
    int beg = rowptr[node], end = rowptr[node + 1];
    float dd = dinv[node]; dd *= dd;
    bool act = lane < (COUT / 2);
    float accA = 0.f, accB = 0.f;
    if (act) {
        unsigned u = __ldg((const unsigned*)(in + (size_t)node * COUT) + lane);
        float2 f = u2f2(u);
        accA = dd * f.x; accB = dd * f.y;
    }
    int j = beg;
    for (; j + 2 <= end; j += 2) {
        int2 e0 = __ldg(edge + j), e1 = __ldg(edge + j + 1);
        float w0 = __int_as_float(e0.y), w1 = __int_as_float(e1.y);
        if (act) {
            unsigned u0 = __ldg((const unsigned*)(in + (size_t)e0.x * COUT) + lane);
            unsigned u1 = __ldg((const unsigned*)(in + (size_t)e1.x * COUT) + lane);
            float2 f0 = u2f2(u0), f1 = u2f2(u1);
            accA = fmaf(w0, f0.x, fmaf(w1, f1.x, accA));
            accB = fmaf(w0, f0.y, fmaf(w1, f1.y, accB));
        }
    }
    if (j < end) {
        int2 e0 = __ldg(edge + j);
        float w = __int_as_float(e0.y);
        if (act) {
            unsigned u0 = __ldg((const unsigned*)(in + (size_t)e0.x * COUT) + lane);
            float2 f0 = u2f2(u0);
            accA = fmaf(w, f0.x, accA);
            accB = fmaf(w, f0.y, accB);
        }
    }
    float mx = act ? fmaxf(accA, accB) : -INFINITY;
#pragma unroll
    for (int o = 16; o > 0; o >>= 1) mx = fmaxf(mx, __shfl_xor_sync(0xffffffffu, mx, o));
    float s = act ? (expf(accA - mx) + expf(accB - mx)) : 0.f;
#pragma unroll
    for (int o = 16; o > 0; o >>= 1) s += __shfl_xor_sync(0xffffffffu, s, o);
    float ls = logf(s);
    if (act) {
        float2 o2 = make_float2(accA - mx - ls, accB - mx - ls);
        *((float2*)(out + (size_t)node * COUT) + lane) = o2;
    }
}

// ---------------- host ----------------
static inline int cdiv(int a, int b) { return (a + b - 1) / b; }

extern "C" void kernel_launch(void* const* d_in, const int* in_sizes, int n_in,
                              void* d_out, int out_size) {
    const float* x    = (const float*)d_in[0];
    const int*   ei   = (const int*)d_in[1];
    const float* W1   = (const float*)d_in[2];
    const float* b1   = (const float*)d_in[3];
    const float* a1   = (const float*)d_in[4];
    const float* W2   = (const float*)d_in[5];
    const float* b2   = (const float*)d_in[6];
    const float* a2   = (const float*)d_in[7];
    const float* g2   = (const float*)d_in[8];
    const float* W3   = (const float*)d_in[9];
    const float* b3   = (const float*)d_in[10];
    const float* a3   = (const float*)d_in[11];
    const float* g3   = (const float*)d_in[12];
    const float* bn1g = (const float*)d_in[13];
    const float* bn1b = (const float*)d_in[14];
    const float* bn2g = (const float*)d_in[15];
    const float* bn2b = (const float*)d_in[16];

    const int N = in_sizes[0] / KDIM;
    const int E = in_sizes[1] / 2;
    const int* src = ei;
    const int* dst = ei + E;

    float *buf1, *buf2, *dinv, *Wq1, *Wq2, *Wq3, *stats1, *stats2;
    __half* hbuf;
    int *deg, *rowptr, *cursor, *tpref, *bsum;
    int2* edge;
    cudaGetSymbolAddress((void**)&buf1,   g_buf1);
    cudaGetSymbolAddress((void**)&buf2,   g_buf2);
    cudaGetSymbolAddress((void**)&hbuf,   g_hbuf);
    cudaGetSymbolAddress((void**)&dinv,   g_dinv);
    cudaGetSymbolAddress((void**)&deg,    g_deg);
    cudaGetSymbolAddress((void**)&rowptr, g_rowptr);
    cudaGetSymbolAddress((void**)&cursor, g_cursor);
    cudaGetSymbolAddress((void**)&edge,   g_edge);
    cudaGetSymbolAddress((void**)&Wq1,    g_Wq1);
    cudaGetSymbolAddress((void**)&Wq2,    g_Wq2);
    cudaGetSymbolAddress((void**)&Wq3,    g_Wq3);
    cudaGetSymbolAddress((void**)&stats1, g_stats1);
    cudaGetSymbolAddress((void**)&stats2, g_stats2);
    cudaGetSymbolAddress((void**)&tpref,  g_tpref);
    cudaGetSymbolAddress((void**)&bsum,   g_bsum);

    const int TB = 256;
    const int GB = cdiv(N, TROWS);

    k_pre<<<cdiv(E, TB), TB>>>(dst, deg, E, W1, a1, W2, a2, W3, a3, Wq1, Wq2, Wq3);
    k_scan_p1<<<SCAN_B, SCAN_T>>>(deg, dinv, tpref, bsum, N);
    k_scan_p3<<<SCAN_B, SCAN_T>>>(deg, tpref, bsum, rowptr, cursor, N, E);
    // layer-1 GEMM at launch index 3 (ncu capture target)
    k_gemm_tiled<false><<<GB, 256>>>(x, Wq1, b1, hbuf, nullptr, nullptr, nullptr, nullptr, N);
    k_scatter<<<cdiv(E, TB), TB>>>(src, dst, dinv, cursor, edge, deg, E, N);

    // ---- layer 1 aggregation (fp16 messages) ----
    k_agg_csr128_stats<<<AGG_BLOCKS, 256>>>(rowptr, edge, dinv, hbuf, buf2, stats1, N);

    // ---- layer 2 ----
    k_gemm_tiled<true><<<GB, 256>>>(buf2, Wq2, b2, hbuf, stats1, bn1g, bn1b, g2, N);
    k_agg_csr128_stats<<<AGG_BLOCKS, 256>>>(rowptr, edge, dinv, hbuf, buf1, stats2, N);

    // ---- layer 3 ----
    k_gemm40<<<cdiv(N * 32, TB), TB>>>(buf1, Wq3, b3, hbuf, stats2, bn2g, bn2b, g3, N);
    k_agg40_lsm<<<cdiv(N * 32, TB), TB>>>(rowptr, edge, dinv, hbuf, (float*)d_out,
                                          stats1, stats2, N);
}